// round 4
// baseline (speedup 1.0000x reference)
#include <cuda_runtime.h>
#include <cuda_bf16.h>
#include <math.h>

// reconstruction_loss: Charbonnier mean over MSFA(4)-mosaic-gathered pixels.
//   X, Y: [B=8, C=16, H=512, W=512] fp32; c = (h%4)*4 + (w%4)
//   out:  scalar mean_{b,h,w} sqrt((X-Y)^2 + 1e-6) over gathered pixels.
//
// R3: single fused kernel. Block partials are accumulated into a 64-bit
// fixed-point (x 2^32) integer via atomicAdd -> order-independent, hence
// deterministic across graph replays. Last block writes d_out and resets
// the device-global state for the next replay.

#define BLOCKS   1024
#define THREADS  256
#define NTHREADS (BLOCKS * THREADS)     // 262144
#define ITERS    8                      // 262144 * 8 = 2097152 = B*H*W exactly
#define TOTAL_PIX 2097152u
#define FIXSCALE 4294967296.0           // 2^32

__device__ unsigned long long g_acc;    // zero-initialized at module load
__device__ unsigned int       g_count;

__global__ void __launch_bounds__(THREADS)
msfa_charbonnier_fused(const float* __restrict__ X,
                       const float* __restrict__ Y,
                       float* __restrict__ out) {
    unsigned tid = blockIdx.x * THREADS + threadIdx.x;

    float acc = 0.0f;
#pragma unroll
    for (int k = 0; k < ITERS; k++) {
        unsigned e = tid + (unsigned)k * NTHREADS;
        unsigned b = e >> 18;               // / (512*512)
        unsigned h = (e >> 9) & 511u;
        unsigned w = e & 511u;
        unsigned c = ((h & 3u) << 2) | (w & 3u);
        unsigned off = (((b << 4) | c) << 18) | (h << 9) | w;
        float d = __ldg(X + off) - __ldg(Y + off);
        acc += sqrtf(fmaf(d, d, 1e-6f));
    }

    // warp reduce
#pragma unroll
    for (int s = 16; s > 0; s >>= 1)
        acc += __shfl_xor_sync(0xffffffffu, acc, s);

    __shared__ float sm[THREADS / 32];
    if ((threadIdx.x & 31u) == 0u)
        sm[threadIdx.x >> 5] = acc;
    __syncthreads();

    if (threadIdx.x == 0) {
        float p = 0.0f;
#pragma unroll
        for (int i = 0; i < THREADS / 32; i++)
            p += sm[i];

        // Fixed-point accumulate: integer adds are commutative -> deterministic.
        unsigned long long q =
            (unsigned long long)__double2ll_rn((double)p * FIXSCALE);
        atomicAdd(&g_acc, q);
        __threadfence();

        unsigned prev = atomicAdd(&g_count, 1u);
        if (prev == BLOCKS - 1) {
            __threadfence();
            unsigned long long s = *(volatile unsigned long long*)&g_acc;
            double sum = (double)(long long)s * (1.0 / FIXSCALE);
            out[0] = (float)(sum / (double)TOTAL_PIX);
            // Reset for next graph replay (visible at next kernel launch).
            g_acc   = 0ULL;
            g_count = 0u;
        }
    }
}

extern "C" void kernel_launch(void* const* d_in, const int* in_sizes, int n_in,
                              void* d_out, int out_size) {
    const float* X = (const float*)d_in[0];
    const float* Y = (const float*)d_in[1];
    float* out = (float*)d_out;

    msfa_charbonnier_fused<<<BLOCKS, THREADS>>>(X, Y, out);
}

// round 6
// speedup vs baseline: 1.1654x; 1.1654x over previous
#include <cuda_runtime.h>
#include <cuda_bf16.h>
#include <math.h>

// reconstruction_loss: Charbonnier mean over MSFA(4)-mosaic-gathered pixels.
//   X, Y: [B=8, C=16, H=512, W=512] fp32; c = (h%4)*4 + (w%4)
//   out = mean_{b,h,w} sqrt((X[b,c,h,w]-Y[b,c,h,w])^2 + 1e-6)
//
// R4: fused single kernel, R2 grid geometry (2048x256), explicit front-batched
// loads. Key identity: e = tid + k*2^19 keeps (h,w,c) invariant in k, and the
// gather offset advances by exactly k*2^23 elements -> 8 independent LDGs at
// base + k*DELTA, no per-iter index math.

#define BLOCKS   2048
#define THREADS  256
#define NTHREADS (BLOCKS * THREADS)       // 524288 = 2^19
#define ITERS    4                        // 2^19 * 4 = 2097152 = B*H*W
#define TOTAL_PIX 2097152u
#define DELTA    (1u << 23)               // advance 2 batches * 16 ch * 2^18
#define FIXSCALE 4294967296.0             // 2^32

__device__ unsigned long long g_acc;      // zero-init at module load
__device__ unsigned int       g_count;

__global__ void __launch_bounds__(THREADS)
msfa_charbonnier_fused(const float* __restrict__ X,
                       const float* __restrict__ Y,
                       float* __restrict__ out) {
    unsigned tid = blockIdx.x * THREADS + threadIdx.x;   // < 2^19

    // Decode invariant coordinates once.
    unsigned b0 = tid >> 18;                 // 0 or 1
    unsigned h  = (tid >> 9) & 511u;
    unsigned w  = tid & 511u;
    unsigned c  = ((h & 3u) << 2) | (w & 3u);
    unsigned off0 = (((b0 << 4) | c) << 18) | (h << 9) | w;

    // Front-batched independent loads: 8 LDGs in flight per thread.
    float xv[ITERS], yv[ITERS];
#pragma unroll
    for (int k = 0; k < ITERS; k++)
        xv[k] = __ldg(X + off0 + (unsigned)k * DELTA);
#pragma unroll
    for (int k = 0; k < ITERS; k++)
        yv[k] = __ldg(Y + off0 + (unsigned)k * DELTA);

    float acc = 0.0f;
#pragma unroll
    for (int k = 0; k < ITERS; k++) {
        float d = xv[k] - yv[k];
        acc += sqrtf(fmaf(d, d, 1e-6f));
    }

    // warp reduce
#pragma unroll
    for (int s = 16; s > 0; s >>= 1)
        acc += __shfl_xor_sync(0xffffffffu, acc, s);

    __shared__ float sm[THREADS / 32];
    if ((threadIdx.x & 31u) == 0u)
        sm[threadIdx.x >> 5] = acc;
    __syncthreads();

    if (threadIdx.x == 0) {
        float p = 0.0f;
#pragma unroll
        for (int i = 0; i < THREADS / 32; i++)
            p += sm[i];

        // Fixed-point accumulate: integer adds commute -> deterministic.
        unsigned long long q =
            (unsigned long long)__double2ll_rn((double)p * FIXSCALE);
        atomicAdd(&g_acc, q);
        __threadfence();

        unsigned prev = atomicAdd(&g_count, 1u);
        if (prev == BLOCKS - 1) {
            __threadfence();
            unsigned long long s = *(volatile unsigned long long*)&g_acc;
            double sum = (double)(long long)s * (1.0 / FIXSCALE);
            out[0] = (float)(sum / (double)TOTAL_PIX);
            // Reset for the next graph replay.
            g_acc   = 0ULL;
            g_count = 0u;
        }
    }
}

extern "C" void kernel_launch(void* const* d_in, const int* in_sizes, int n_in,
                              void* d_out, int out_size) {
    const float* X = (const float*)d_in[0];
    const float* Y = (const float*)d_in[1];
    float* out = (float*)d_out;

    msfa_charbonnier_fused<<<BLOCKS, THREADS>>>(X, Y, out);
}

// round 7
// speedup vs baseline: 1.3881x; 1.1910x over previous
#include <cuda_runtime.h>
#include <cuda_bf16.h>
#include <math.h>

// reconstruction_loss: Charbonnier mean over MSFA(4)-mosaic-gathered pixels.
//   X, Y: [B=8, C=16, H=512, W=512] fp32; c = (h%4)*4 + (w%4)
//   out = mean_{b,h,w} sqrt((X[b,c,h,w]-Y[b,c,h,w])^2 + 1e-6)
//
// R6: single-wave grid (1024x256 = 262144 threads, ~7 blocks/SM), 8 pixels
// per thread walking h in steps of 4 (same channel, same plane). All 8 loads
// per tensor are [base + k*8KiB] -> one address register + immediate offsets,
// so ptxas front-batches 16 independent LDGs per thread (MLP_p1 = 16).
// Deterministic fixed-point (x2^32) integer atomic reduction, last block
// writes the scalar and resets state for the next graph replay.

#define BLOCKS   1024
#define THREADS  256
#define ITERS    8
#define TOTAL_PIX 2097152u                 // 8*512*512
#define KSTRIDE  2048u                     // 4 rows * 512 floats = 8 KiB
#define FIXSCALE 4294967296.0              // 2^32

__device__ unsigned long long g_acc;       // zero-init at module load
__device__ unsigned int       g_count;

__global__ void __launch_bounds__(THREADS, 8)
msfa_charbonnier_fused(const float* __restrict__ X,
                       const float* __restrict__ Y,
                       float* __restrict__ out) {
    unsigned tid = blockIdx.x * THREADS + threadIdx.x;   // < 2^18

    // tid -> (b, hlow, hm, w); thread covers h = hlow + 32*hm + 4k, k=0..7
    unsigned w    = tid & 511u;
    unsigned t    = tid >> 9;
    unsigned hm   = t & 15u;
    unsigned hlow = (t >> 4) & 3u;
    unsigned b    = t >> 6;                 // [0,8)

    unsigned c    = (hlow << 2) | (w & 3u);     // mosaic channel (k-invariant)
    unsigned off0 = (((b << 4) | c) << 18)      // plane base
                  | ((hlow + (hm << 5)) << 9)   // row h(k=0)
                  | w;

    const float* xp = X + off0;
    const float* yp = Y + off0;

    // 16 independent loads, immediate offsets only.
    float xv[ITERS], yv[ITERS];
#pragma unroll
    for (int k = 0; k < ITERS; k++)
        xv[k] = __ldg(xp + (unsigned)k * KSTRIDE);
#pragma unroll
    for (int k = 0; k < ITERS; k++)
        yv[k] = __ldg(yp + (unsigned)k * KSTRIDE);

    float acc = 0.0f;
#pragma unroll
    for (int k = 0; k < ITERS; k++) {
        float d = xv[k] - yv[k];
        acc += sqrtf(fmaf(d, d, 1e-6f));
    }

    // warp reduce
#pragma unroll
    for (int s = 16; s > 0; s >>= 1)
        acc += __shfl_xor_sync(0xffffffffu, acc, s);

    __shared__ float sm[THREADS / 32];
    if ((threadIdx.x & 31u) == 0u)
        sm[threadIdx.x >> 5] = acc;
    __syncthreads();

    if (threadIdx.x == 0) {
        float p = 0.0f;
#pragma unroll
        for (int i = 0; i < THREADS / 32; i++)
            p += sm[i];

        // Fixed-point accumulate: integer adds commute -> deterministic.
        unsigned long long q =
            (unsigned long long)__double2ll_rn((double)p * FIXSCALE);
        atomicAdd(&g_acc, q);
        __threadfence();

        unsigned prev = atomicAdd(&g_count, 1u);
        if (prev == BLOCKS - 1) {
            __threadfence();
            unsigned long long s = *(volatile unsigned long long*)&g_acc;
            double sum = (double)(long long)s * (1.0 / FIXSCALE);
            out[0] = (float)(sum / (double)TOTAL_PIX);
            // Reset for the next graph replay.
            g_acc   = 0ULL;
            g_count = 0u;
        }
    }
}

extern "C" void kernel_launch(void* const* d_in, const int* in_sizes, int n_in,
                              void* d_out, int out_size) {
    const float* X = (const float*)d_in[0];
    const float* Y = (const float*)d_in[1];
    float* out = (float*)d_out;

    msfa_charbonnier_fused<<<BLOCKS, THREADS>>>(X, Y, out);
}